// round 13
// baseline (speedup 1.0000x reference)
#include <cuda_runtime.h>
#include <cstdint>

// 2x nearest-neighbor upsample: [B*C, 256, 256] f32 -> [B*C, 512, 512] f32.
// One thread per (bc, h2 in [0,128), ow4a in [0,64)) covering:
//   input rows {h2, h2+128} x input float2 cols {ow4a, ow4a+64}
// -> 4 front-batched coalesced LDG.64 + 8 independent coalesced STG.128
//    (output rows {2h2, 2h2+1, 2h2+256, 2h2+257}, cols {ow4a, ow4a+64}).

constexpr int IW2 = 128;     // input float2s per row
constexpr int OW4 = 128;     // output float4s per row

__global__ void __launch_bounds__(256) upsample2x_kernel(
        const float2* __restrict__ in,
        float4* __restrict__ out,
        int total) {
    int i = blockIdx.x * blockDim.x + threadIdx.x;
    if (i >= total) return;

    // i = ((bc * 128) + h2) * 64 + ow4a
    int ow4a = i & 63;
    int t    = i >> 6;
    int h2   = t & 127;
    int bc   = t >> 7;

    long ibase = ((long)(bc << 8) + h2) * IW2 + ow4a;
    const long IROW128 = (long)128 * IW2;           // 128 input rows

    float2 va = in[ibase];
    float2 vb = in[ibase + 64];
    float2 vc = in[ibase + IROW128];
    float2 vd = in[ibase + IROW128 + 64];

    float4 fa = make_float4(va.x, va.x, va.y, va.y);
    float4 fb = make_float4(vb.x, vb.x, vb.y, vb.y);
    float4 fc = make_float4(vc.x, vc.x, vc.y, vc.y);
    float4 fd = make_float4(vd.x, vd.x, vd.y, vd.y);

    long obase = ((long)(bc << 9) + (h2 << 1)) * OW4 + ow4a;
    const long OROW256 = (long)256 * OW4;           // 256 output rows

    out[obase]                  = fa;
    out[obase + 64]             = fb;
    out[obase + OW4]            = fa;
    out[obase + OW4 + 64]       = fb;
    out[obase + OROW256]            = fc;
    out[obase + OROW256 + 64]       = fd;
    out[obase + OROW256 + OW4]      = fc;
    out[obase + OROW256 + OW4 + 64] = fd;
}

extern "C" void kernel_launch(void* const* d_in, const int* in_sizes, int n_in,
                              void* d_out, int out_size) {
    const float2* in = (const float2*)d_in[0];
    float4* out = (float4*)d_out;
    // one thread per 8 input floats: 67,108,864 / 8 = 8,388,608
    int total = in_sizes[0] >> 3;

    int block = 256;
    int grid = (total + block - 1) / block;
    upsample2x_kernel<<<grid, block>>>(in, out, total);
}

// round 17
// speedup vs baseline: 1.0215x; 1.0215x over previous
#include <cuda_runtime.h>
#include <cstdint>

// 2x nearest-neighbor upsample: [B*C, 256, 256] f32 -> [B*C, 512, 512] f32.
// R9 work-shape (best measured): one thread per (bc, h, ow4a in [0,64)),
// 2 coalesced LDG.64 + 4 coalesced STG.128 — now with streaming cache hints:
//   __ldcs on input (read once), __stcs on output (written once, never re-read)
// to keep the 1GB write stream from occupying L2 and improve writeback drain.

constexpr int IW2 = 128;     // input float2s per row
constexpr int OW4 = 128;     // output float4s per row

__global__ void __launch_bounds__(256) upsample2x_kernel(
        const float2* __restrict__ in,
        float4* __restrict__ out,
        int total) {
    int i = blockIdx.x * blockDim.x + threadIdx.x;
    if (i >= total) return;

    // i = ((bc * 256) + h) * 64 + ow4a
    int ow4a = i & 63;
    int t    = i >> 6;
    int h    = t & 255;
    int bc   = t >> 8;

    long ibase = ((long)(bc << 8) + h) * IW2 + ow4a;
    float2 va = __ldcs(&in[ibase]);
    float2 vb = __ldcs(&in[ibase + 64]);

    float4 fa = make_float4(va.x, va.x, va.y, va.y);
    float4 fb = make_float4(vb.x, vb.x, vb.y, vb.y);

    long obase = ((long)(bc << 9) + (h << 1)) * OW4 + ow4a;

    __stcs(&out[obase],            fa);
    __stcs(&out[obase + 64],       fb);
    __stcs(&out[obase + OW4],      fa);
    __stcs(&out[obase + OW4 + 64], fb);
}

extern "C" void kernel_launch(void* const* d_in, const int* in_sizes, int n_in,
                              void* d_out, int out_size) {
    const float2* in = (const float2*)d_in[0];
    float4* out = (float4*)d_out;
    // one thread per 4 input floats: 67,108,864 / 4 = 16,777,216
    int total = in_sizes[0] >> 2;

    int block = 256;
    int grid = (total + block - 1) / block;
    upsample2x_kernel<<<grid, block>>>(in, out, total);
}